// round 12
// baseline (speedup 1.0000x reference)
#include <cuda_runtime.h>

#define NN 100000
#define EMAX 3200000

// ---- scratch (no allocations allowed; __device__ globals) ----
__device__ int   g_deg[NN];
__device__ float g_dis[NN];
__device__ int   g_rowstart[NN + 1];
__device__ int   g_cursor[NN];
__device__ int   g_srcs[EMAX];
__device__ __align__(16) float g_hs1[NN * 32];   // dis-scaled x@W1^T
__device__ __align__(16) float g_y1 [NN * 32];   // relu(layer1)
__device__ __align__(16) float g_hs2[NN * 16];   // dis-scaled y1@W2^T
__device__ int   g_is64;

// ---------------- init + edge-index dtype detection ----------------
// jnp.int64 demotes to int32 unless x64 is enabled; element counts are
// identical either way (6.4M), so sniff the payload: true int64 values
// < 100000 have all-zero high words (odd int32 slots).
__global__ void k_init(const int* __restrict__ ei32) {
    int i = blockIdx.x * blockDim.x + threadIdx.x;
    if (i < NN) g_deg[i] = 1;                     // self-loop counts toward degree
    if (i == 0) {
        int any = 0;
        for (int k = 1; k < 64; k += 2) any |= ei32[k];
        g_is64 = (any == 0) ? 1 : 0;
    }
}

__device__ __forceinline__ int edge_src(const void* ei, int E, int e) {
    return g_is64 ? (int)((const long long*)ei)[e] : ((const int*)ei)[e];
}
__device__ __forceinline__ int edge_dst(const void* ei, int E, int e) {
    return g_is64 ? (int)((const long long*)ei)[E + e] : ((const int*)ei)[E + e];
}

// ---------------- CSR build ----------------
__global__ void k_count(const void* __restrict__ ei, int E) {
    int e = blockIdx.x * blockDim.x + threadIdx.x;
    if (e < E) {
        int d = edge_dst(ei, E, e);
        if ((unsigned)d < NN) atomicAdd(&g_deg[d], 1);   // guard: misdetect -> wrong, not crash
    }
}

// Fused scan (replaces scan1+scan2+scan3): single block, thread t serially
// scans its 98 nodes, block-scan of the 1024 partials, then writes
// rowstart + cursor (cursor doubles as the fill write pointer). Also dis.
#define SCAN_T   1024
#define SCAN_PER 98          // 1024*98 = 100352 >= NN
__global__ void k_scanA(int E) {
    __shared__ int sh[SCAN_T];
    int t = threadIdx.x;
    int base = t * SCAN_PER;
    int local = 0;
    for (int k = 0; k < SCAN_PER; k++) {
        int i = base + k;
        if (i < NN) {
            int d = g_deg[i];
            g_dis[i] = rsqrtf((float)d);
            local += d - 1;
        }
    }
    sh[t] = local;
    __syncthreads();
    for (int off = 1; off < SCAN_T; off <<= 1) {
        int x = (t >= off) ? sh[t - off] : 0;
        __syncthreads();
        sh[t] += x;
        __syncthreads();
    }
    int run = sh[t] - local;                      // exclusive prefix for this thread
    for (int k = 0; k < SCAN_PER; k++) {
        int i = base + k;
        if (i < NN) {
            g_rowstart[i] = run;
            g_cursor[i]   = run;
            run += g_deg[i] - 1;
        }
    }
    if (t == 0) g_rowstart[NN] = E;
}

__global__ void k_fill(const void* __restrict__ ei, int E) {
    int e = blockIdx.x * blockDim.x + threadIdx.x;
    if (e < E) {
        int d = edge_dst(ei, E, e);
        if ((unsigned)d < NN) {
            int pos = atomicAdd(&g_cursor[d], 1);
            int s = edge_src(ei, E, e);
            g_srcs[pos] = ((unsigned)s < NN) ? s : 0;
        }
    }
}

// ---------------- layer 1 transform: hs1 = dis[n] * (x[n] @ W1^T) ----------------
__global__ void k_gemm1(const float* __restrict__ x, const float* __restrict__ W1) {
    __shared__ float4 sW[32 * 32];                 // W1 [32,128] as float4
    for (int i = threadIdx.x; i < 1024; i += blockDim.x)
        sW[i] = ((const float4*)W1)[i];
    __syncthreads();
    int n = blockIdx.x * blockDim.x + threadIdx.x;
    if (n >= NN) return;
    float acc[32];
#pragma unroll
    for (int j = 0; j < 32; j++) acc[j] = 0.f;
    const float4* xr = (const float4*)(x + (size_t)n * 128);
#pragma unroll 8
    for (int k4 = 0; k4 < 32; k4++) {
        float4 xv = xr[k4];
#pragma unroll
        for (int j = 0; j < 32; j++) {
            float4 w = sW[j * 32 + k4];
            acc[j] += xv.x * w.x + xv.y * w.y + xv.z * w.z + xv.w * w.w;
        }
    }
    float dv = g_dis[n];
    float4* o = (float4*)(g_hs1 + (size_t)n * 32);
#pragma unroll
    for (int j = 0; j < 8; j++)
        o[j] = make_float4(acc[4*j] * dv, acc[4*j+1] * dv, acc[4*j+2] * dv, acc[4*j+3] * dv);
}

// ---------------- layer 1 aggregate: warp per node, 32 lanes = 32 feats ----------------
// Minimal inner loop: 1 coalesced LDG (one 128B line) + 1 FADD per edge.
__global__ void k_agg1(const float* __restrict__ b1) {
    int gt = blockIdx.x * blockDim.x + threadIdx.x;
    int v = gt >> 5, lane = threadIdx.x & 31;
    if (v >= NN) return;
    float acc = g_hs1[v * 32 + lane];              // self-loop term (already dis-scaled)
    int s0 = g_rowstart[v], s1 = g_rowstart[v + 1];
    for (int base = s0; base < s1; base += 32) {
        int idx = base + lane;
        int sv = g_srcs[idx < s1 ? idx : s1 - 1];
        int cnt = s1 - base;
        if (cnt >= 32) {
#pragma unroll
            for (int j = 0; j < 32; j++) {
                int s = __shfl_sync(0xffffffffu, sv, j);
                acc += g_hs1[s * 32 + lane];       // coalesced 128B line / edge
            }
        } else {
            for (int j = 0; j < cnt; j++) {
                int s = __shfl_sync(0xffffffffu, sv, j);
                acc += g_hs1[s * 32 + lane];
            }
        }
    }
    float r = g_dis[v] * acc + b1[lane];
    g_y1[v * 32 + lane] = fmaxf(r, 0.f);
}

// ---------------- layer 2 transform: hs2 = dis[n] * (y1[n] @ W2^T) ----------------
__global__ void k_gemm2(const float* __restrict__ W2) {
    __shared__ float sW[512];                      // W2 [16,32]
    for (int i = threadIdx.x; i < 512; i += blockDim.x) sW[i] = W2[i];
    __syncthreads();
    int n = blockIdx.x * blockDim.x + threadIdx.x;
    if (n >= NN) return;
    float xin[32];
    const float4* yr = (const float4*)(g_y1 + (size_t)n * 32);
#pragma unroll
    for (int k4 = 0; k4 < 8; k4++) {
        float4 t = yr[k4];
        xin[4*k4] = t.x; xin[4*k4+1] = t.y; xin[4*k4+2] = t.z; xin[4*k4+3] = t.w;
    }
    float dv = g_dis[n];
#pragma unroll
    for (int j = 0; j < 16; j++) {
        float a = 0.f;
#pragma unroll
        for (int k = 0; k < 32; k++) a += xin[k] * sW[j * 32 + k];
        g_hs2[n * 16 + j] = a * dv;
    }
}

// ---------------- layer 2 aggregate + fused LSTM + output proj ----------------
// 16 lanes per node; two nodes per warp (R9-proven). y2 never hits memory.
__global__ void k_agg2(const float* __restrict__ b2, const float* __restrict__ w_ih,
                       const float* __restrict__ b_ih, const float* __restrict__ b_hh,
                       const float* __restrict__ W_out, const float* __restrict__ b_out,
                       float* __restrict__ out) {
    int gt = blockIdx.x * blockDim.x + threadIdx.x;
    int v = gt >> 4;
    int lane = threadIdx.x & 31;
    int gl = lane & 15;
    unsigned gmask = 0xFFFFu << (lane & 16);       // own half-warp only (groups may diverge)
    if (v >= NN) return;

    float acc = g_hs2[v * 16 + gl];                // self-loop
    int s0 = g_rowstart[v], s1 = g_rowstart[v + 1];
    for (int base = s0; base < s1; base += 16) {
        int idx = base + gl;
        int sv = g_srcs[idx < s1 ? idx : s1 - 1];
        int cnt = s1 - base;
        if (cnt >= 16) {
#pragma unroll
            for (int j = 0; j < 16; j++) {
                int s = __shfl_sync(gmask, sv, j, 16);
                acc += g_hs2[s * 16 + gl];
            }
        } else {
            for (int j = 0; j < cnt; j++) {
                int s = __shfl_sync(gmask, sv, j, 16);
                acc += g_hs2[s * 16 + gl];
            }
        }
    }
    float y2 = fmaxf(g_dis[v] * acc + b2[gl], 0.f);

    // LSTM (h0=c0=0): gates i,g,o only (f multiplies c0=0; w_hh term zero).
    int j = gl & 7;
    float ai = b_ih[j]      + b_hh[j];
    float ag = b_ih[16 + j] + b_hh[16 + j];
    float ao = b_ih[24 + j] + b_hh[24 + j];
#pragma unroll
    for (int k = 0; k < 16; k++) {
        float vv = __shfl_sync(gmask, y2, k, 16);
        ai += w_ih[j * 16 + k]        * vv;
        ag += w_ih[(16 + j) * 16 + k] * vv;
        ao += w_ih[(24 + j) * 16 + k] * vv;
    }
    float c  = (1.f / (1.f + __expf(-ai))) * tanhf(ag);
    float hh = (1.f / (1.f + __expf(-ao))) * tanhf(c);
    float part = (gl < 8) ? hh * W_out[j] : 0.f;
#pragma unroll
    for (int off = 8; off; off >>= 1)
        part += __shfl_xor_sync(gmask, part, off, 16);
    if (gl == 0) out[v] = part + b_out[0];
}

// ---------------- launch ----------------
extern "C" void kernel_launch(void* const* d_in, const int* in_sizes, int n_in,
                              void* d_out, int out_size) {
    const float* x     = (const float*)d_in[0];
    const void*  ei    = d_in[1];
    const float* W1    = (const float*)d_in[2];
    const float* b1    = (const float*)d_in[3];
    const float* W2    = (const float*)d_in[4];
    const float* b2    = (const float*)d_in[5];
    const float* w_ih  = (const float*)d_in[6];
    // d_in[7] = w_hh: unused (h0 == 0)
    const float* b_ih  = (const float*)d_in[8];
    const float* b_hh  = (const float*)d_in[9];
    const float* W_out = (const float*)d_in[10];
    const float* b_out = (const float*)d_in[11];
    float*       out   = (float*)d_out;

    int E = in_sizes[1] / 2;   // element count is 6.4M for both int32 and int64

    k_init  <<<(NN + 255) / 256, 256>>>((const int*)ei);          // 1
    k_count <<<(E + 255) / 256, 256>>>(ei, E);                    // 2
    k_scanA <<<1, SCAN_T>>>(E);                                   // 3
    k_fill  <<<(E + 255) / 256, 256>>>(ei, E);                    // 4
    k_gemm1 <<<(NN + 127) / 128, 128>>>(x, W1);                   // 5
    k_agg1  <<<(NN * 32 + 255) / 256, 256>>>(b1);                 // 6  <- ncu -s 5 samples this
    k_gemm2 <<<(NN + 255) / 256, 256>>>(W2);                      // 7
    k_agg2  <<<(NN * 16 + 255) / 256, 256>>>(b2, w_ih, b_ih, b_hh, W_out, b_out, out);  // 8
}

// round 13
// speedup vs baseline: 1.9162x; 1.9162x over previous
#include <cuda_runtime.h>

#define NN 100000
#define EMAX 3200000

// ---- scratch (no allocations allowed; __device__ globals) ----
__device__ int   g_deg[NN];
__device__ float g_dis[NN];
__device__ int   g_rowstart[NN + 1];
__device__ int   g_cursor[NN];
__device__ int   g_srcs[EMAX];
__device__ __align__(16) float g_hs1[NN * 32];   // dis-scaled x@W1^T
__device__ __align__(16) float g_y1 [NN * 32];   // relu(layer1)
__device__ __align__(16) float g_hs2[NN * 16];   // dis-scaled y1@W2^T
__device__ int   g_bsum[128];
__device__ int   g_is64;

// ---------------- init + edge-index dtype detection ----------------
// jnp.int64 demotes to int32 unless x64 is enabled; element counts are
// identical either way (6.4M), so sniff the payload: true int64 values
// < 100000 have all-zero high words (odd int32 slots).
__global__ void k_init(const int* __restrict__ ei32) {
    int i = blockIdx.x * blockDim.x + threadIdx.x;
    if (i < NN) g_deg[i] = 1;                     // self-loop counts toward degree
    if (i == 0) {
        int any = 0;
        for (int k = 1; k < 64; k += 2) any |= ei32[k];
        g_is64 = (any == 0) ? 1 : 0;
    }
}

__device__ __forceinline__ int edge_src(const void* ei, int E, int e) {
    return g_is64 ? (int)((const long long*)ei)[e] : ((const int*)ei)[e];
}
__device__ __forceinline__ int edge_dst(const void* ei, int E, int e) {
    return g_is64 ? (int)((const long long*)ei)[E + e] : ((const int*)ei)[E + e];
}

// ---------------- CSR build ----------------
// 4 grid-stride phases per thread: coalesced within each phase, 4 independent
// LDG->atomic chains in flight (attacks the measured issue=6.3% latency bind).
__global__ void k_count(const void* __restrict__ ei, int E, int T) {
    int t = blockIdx.x * blockDim.x + threadIdx.x;
#pragma unroll
    for (int k = 0; k < 4; k++) {
        int e = t + k * T;
        if (e < E) {
            int d = edge_dst(ei, E, e);
            if ((unsigned)d < NN) atomicAdd(&g_deg[d], 1);  // guard: misdetect -> wrong, not crash
        }
    }
}

// per-block exclusive scan of edge counts (deg-1); also dis = rsqrt(deg)
__global__ void k_scan1() {
    __shared__ int sh[1024];
    int t = threadIdx.x;
    int i = blockIdx.x * 1024 + t;
    int v = (i < NN) ? (g_deg[i] - 1) : 0;
    if (i < NN) g_dis[i] = rsqrtf((float)g_deg[i]);
    sh[t] = v;
    __syncthreads();
    for (int off = 1; off < 1024; off <<= 1) {
        int x = (t >= off) ? sh[t - off] : 0;
        __syncthreads();
        sh[t] += x;
        __syncthreads();
    }
    if (i < NN) g_rowstart[i] = sh[t] - v;       // block-local exclusive
    if (t == 1023) g_bsum[blockIdx.x] = sh[1023];
}

// each block warp-reduces the partials of preceding blocks, then offsets its
// 1024 rowstarts and seeds the fill cursors. Replaces the serial scan2+scan3.
__global__ void k_scanB(int E) {
    __shared__ int s_off;
    int b = blockIdx.x, t = threadIdx.x;
    if (t < 32) {
        int s = 0;
        for (int k = t; k < b; k += 32) s += g_bsum[k];
#pragma unroll
        for (int o = 16; o; o >>= 1) s += __shfl_xor_sync(0xffffffffu, s, o);
        if (t == 0) s_off = s;
    }
    __syncthreads();
    int i = b * 1024 + t;
    if (i < NN) {
        int r = g_rowstart[i] + s_off;
        g_rowstart[i] = r;
        g_cursor[i]   = r;                       // cursor doubles as write pointer
    }
    if (i == NN) g_rowstart[NN] = E;
}

__global__ void k_fill(const void* __restrict__ ei, int E, int T) {
    int t = blockIdx.x * blockDim.x + threadIdx.x;
#pragma unroll
    for (int k = 0; k < 4; k++) {
        int e = t + k * T;
        if (e < E) {
            int d = edge_dst(ei, E, e);
            if ((unsigned)d < NN) {
                int pos = atomicAdd(&g_cursor[d], 1);
                int s = edge_src(ei, E, e);
                g_srcs[pos] = ((unsigned)s < NN) ? s : 0;
            }
        }
    }
}

// ---------------- layer 1 transform: hs1 = dis[n] * (x[n] @ W1^T) ----------------
__global__ void k_gemm1(const float* __restrict__ x, const float* __restrict__ W1) {
    __shared__ float4 sW[32 * 32];                 // W1 [32,128] as float4
    for (int i = threadIdx.x; i < 1024; i += blockDim.x)
        sW[i] = ((const float4*)W1)[i];
    __syncthreads();
    int n = blockIdx.x * blockDim.x + threadIdx.x;
    if (n >= NN) return;
    float acc[32];
#pragma unroll
    for (int j = 0; j < 32; j++) acc[j] = 0.f;
    const float4* xr = (const float4*)(x + (size_t)n * 128);
#pragma unroll 8
    for (int k4 = 0; k4 < 32; k4++) {
        float4 xv = xr[k4];
#pragma unroll
        for (int j = 0; j < 32; j++) {
            float4 w = sW[j * 32 + k4];
            acc[j] += xv.x * w.x + xv.y * w.y + xv.z * w.z + xv.w * w.w;
        }
    }
    float dv = g_dis[n];
    float4* o = (float4*)(g_hs1 + (size_t)n * 32);
#pragma unroll
    for (int j = 0; j < 8; j++)
        o[j] = make_float4(acc[4*j] * dv, acc[4*j+1] * dv, acc[4*j+2] * dv, acc[4*j+3] * dv);
}

// ---------------- layer 1 aggregate: warp per node, 32 lanes = 32 feats ----------------
// Minimal inner loop: 1 coalesced LDG (one 128B line) + 1 FADD per edge (R9-proven).
__global__ void k_agg1(const float* __restrict__ b1) {
    int gt = blockIdx.x * blockDim.x + threadIdx.x;
    int v = gt >> 5, lane = threadIdx.x & 31;
    if (v >= NN) return;
    float acc = g_hs1[v * 32 + lane];              // self-loop term (already dis-scaled)
    int s0 = g_rowstart[v], s1 = g_rowstart[v + 1];
    for (int base = s0; base < s1; base += 32) {
        int idx = base + lane;
        int sv = g_srcs[idx < s1 ? idx : s1 - 1];
        int cnt = s1 - base;
        if (cnt >= 32) {
#pragma unroll
            for (int j = 0; j < 32; j++) {
                int s = __shfl_sync(0xffffffffu, sv, j);
                acc += g_hs1[s * 32 + lane];       // coalesced 128B line / edge
            }
        } else {
            for (int j = 0; j < cnt; j++) {
                int s = __shfl_sync(0xffffffffu, sv, j);
                acc += g_hs1[s * 32 + lane];
            }
        }
    }
    float r = g_dis[v] * acc + b1[lane];
    g_y1[v * 32 + lane] = fmaxf(r, 0.f);
}

// ---------------- layer 2 transform: hs2 = dis[n] * (y1[n] @ W2^T) ----------------
__global__ void k_gemm2(const float* __restrict__ W2) {
    __shared__ float sW[512];                      // W2 [16,32]
    for (int i = threadIdx.x; i < 512; i += blockDim.x) sW[i] = W2[i];
    __syncthreads();
    int n = blockIdx.x * blockDim.x + threadIdx.x;
    if (n >= NN) return;
    float xin[32];
    const float4* yr = (const float4*)(g_y1 + (size_t)n * 32);
#pragma unroll
    for (int k4 = 0; k4 < 8; k4++) {
        float4 t = yr[k4];
        xin[4*k4] = t.x; xin[4*k4+1] = t.y; xin[4*k4+2] = t.z; xin[4*k4+3] = t.w;
    }
    float dv = g_dis[n];
#pragma unroll
    for (int j = 0; j < 16; j++) {
        float a = 0.f;
#pragma unroll
        for (int k = 0; k < 32; k++) a += xin[k] * sW[j * 32 + k];
        g_hs2[n * 16 + j] = a * dv;
    }
}

// ---------------- layer 2 aggregate + fused LSTM + output proj ----------------
// 16 lanes per node; two nodes per warp (R9-proven). y2 never hits memory.
__global__ void k_agg2(const float* __restrict__ b2, const float* __restrict__ w_ih,
                       const float* __restrict__ b_ih, const float* __restrict__ b_hh,
                       const float* __restrict__ W_out, const float* __restrict__ b_out,
                       float* __restrict__ out) {
    int gt = blockIdx.x * blockDim.x + threadIdx.x;
    int v = gt >> 4;
    int lane = threadIdx.x & 31;
    int gl = lane & 15;
    unsigned gmask = 0xFFFFu << (lane & 16);       // own half-warp only (groups may diverge)
    if (v >= NN) return;

    float acc = g_hs2[v * 16 + gl];                // self-loop
    int s0 = g_rowstart[v], s1 = g_rowstart[v + 1];
    for (int base = s0; base < s1; base += 16) {
        int idx = base + gl;
        int sv = g_srcs[idx < s1 ? idx : s1 - 1];
        int cnt = s1 - base;
        if (cnt >= 16) {
#pragma unroll
            for (int j = 0; j < 16; j++) {
                int s = __shfl_sync(gmask, sv, j, 16);
                acc += g_hs2[s * 16 + gl];
            }
        } else {
            for (int j = 0; j < cnt; j++) {
                int s = __shfl_sync(gmask, sv, j, 16);
                acc += g_hs2[s * 16 + gl];
            }
        }
    }
    float y2 = fmaxf(g_dis[v] * acc + b2[gl], 0.f);

    // LSTM (h0=c0=0): gates i,g,o only (f multiplies c0=0; w_hh term zero).
    int j = gl & 7;
    float ai = b_ih[j]      + b_hh[j];
    float ag = b_ih[16 + j] + b_hh[16 + j];
    float ao = b_ih[24 + j] + b_hh[24 + j];
#pragma unroll
    for (int k = 0; k < 16; k++) {
        float vv = __shfl_sync(gmask, y2, k, 16);
        ai += w_ih[j * 16 + k]        * vv;
        ag += w_ih[(16 + j) * 16 + k] * vv;
        ao += w_ih[(24 + j) * 16 + k] * vv;
    }
    float c  = (1.f / (1.f + __expf(-ai))) * tanhf(ag);
    float hh = (1.f / (1.f + __expf(-ao))) * tanhf(c);
    float part = (gl < 8) ? hh * W_out[j] : 0.f;
#pragma unroll
    for (int off = 8; off; off >>= 1)
        part += __shfl_xor_sync(gmask, part, off, 16);
    if (gl == 0) out[v] = part + b_out[0];
}

// ---------------- launch ----------------
extern "C" void kernel_launch(void* const* d_in, const int* in_sizes, int n_in,
                              void* d_out, int out_size) {
    const float* x     = (const float*)d_in[0];
    const void*  ei    = d_in[1];
    const float* W1    = (const float*)d_in[2];
    const float* b1    = (const float*)d_in[3];
    const float* W2    = (const float*)d_in[4];
    const float* b2    = (const float*)d_in[5];
    const float* w_ih  = (const float*)d_in[6];
    // d_in[7] = w_hh: unused (h0 == 0)
    const float* b_ih  = (const float*)d_in[8];
    const float* b_hh  = (const float*)d_in[9];
    const float* W_out = (const float*)d_in[10];
    const float* b_out = (const float*)d_in[11];
    float*       out   = (float*)d_out;

    int E  = in_sizes[1] / 2;   // element count is 6.4M for both int32 and int64
    int T  = (E + 3) / 4;       // phase stride for MLP-4 edge kernels
    int nb = (NN + 1023) / 1024;

    k_init  <<<(NN + 255) / 256, 256>>>((const int*)ei);          // 1
    k_count <<<(T + 255) / 256, 256>>>(ei, E, T);                 // 2
    k_scan1 <<<nb, 1024>>>();                                     // 3
    k_scanB <<<nb, 1024>>>(E);                                    // 4
    k_fill  <<<(T + 255) / 256, 256>>>(ei, E, T);                 // 5
    k_gemm1 <<<(NN + 127) / 128, 128>>>(x, W1);                   // 6  <- ncu -s 5 samples this
    k_agg1  <<<(NN * 32 + 255) / 256, 256>>>(b1);                 // 7
    k_gemm2 <<<(NN + 255) / 256, 256>>>(W2);                      // 8
    k_agg2  <<<(NN * 16 + 255) / 256, 256>>>(b2, w_ih, b_ih, b_hh, W_out, b_out, out);  // 9
}

// round 16
// speedup vs baseline: 1.9265x; 1.0054x over previous
#include <cuda_runtime.h>

#define NN 100000
#define EMAX 3200000

// ---- scratch (no allocations allowed; __device__ globals) ----
__device__ int   g_deg[NN];          // 0-based in-degree (self-loop implicit)
__device__ float g_dis[NN];
__device__ int   g_rowstart[NN + 1];
__device__ int   g_cursor[NN];
__device__ int   g_srcs[EMAX];
__device__ __align__(16) float g_hs1[NN * 32];   // dis-scaled x@W1^T
__device__ __align__(16) float g_y1 [NN * 32];   // relu(layer1)
__device__ __align__(16) float g_hs2[NN * 16];   // dis-scaled y1@W2^T
__device__ int   g_bsum[128];

// Per-block edge-index dtype sniff: jnp.int64 demotes to int32 unless x64 is
// enabled; element counts are identical (6.4M), so check the payload: true
// int64 values < 100000 have all-zero high words (odd int32 slots).
__device__ __forceinline__ int block_is64(const void* ei) {
    __shared__ int s_is64;
    if (threadIdx.x == 0) {
        const int* p = (const int*)ei;
        int any = 0;
        for (int i = 1; i < 64; i += 2) any |= p[i];
        s_is64 = (any == 0) ? 1 : 0;
    }
    __syncthreads();
    return s_is64;
}

// explicit zero each call: unconditional determinism (no cross-call invariant)
__global__ void k_init() {
    int i = blockIdx.x * blockDim.x + threadIdx.x;
    if (i < NN) g_deg[i] = 0;
}

// ---------------- CSR build ----------------
// 4 edges per thread via int4 loads: 1 (int32) or 2 (int64) LDG.128 for the
// dsts, then 4 independent atomic chains in flight.
__global__ void k_count(const void* __restrict__ ei, int E) {
    int is64 = block_is64(ei);
    int t = blockIdx.x * blockDim.x + threadIdx.x;
    int base = t * 4;
    if (base >= E) return;
    if (base + 4 <= E) {
        int d0, d1, d2, d3;
        if (is64) {
            const int4* dst = (const int4*)((const long long*)ei + E);
            int4 a = dst[2 * t], b = dst[2 * t + 1];
            d0 = a.x; d1 = a.z; d2 = b.x; d3 = b.z;
        } else {
            const int4* dst = (const int4*)((const int*)ei + E);
            int4 a = dst[t];
            d0 = a.x; d1 = a.y; d2 = a.z; d3 = a.w;
        }
        if ((unsigned)d0 < NN) atomicAdd(&g_deg[d0], 1);
        if ((unsigned)d1 < NN) atomicAdd(&g_deg[d1], 1);
        if ((unsigned)d2 < NN) atomicAdd(&g_deg[d2], 1);
        if ((unsigned)d3 < NN) atomicAdd(&g_deg[d3], 1);
    } else {
        for (int e = base; e < E; e++) {
            int d = is64 ? (int)((const long long*)ei)[E + e] : ((const int*)ei)[E + e];
            if ((unsigned)d < NN) atomicAdd(&g_deg[d], 1);
        }
    }
}

// per-block exclusive scan of edge counts; dis = rsqrt(deg+1)
__global__ void k_scan1() {
    __shared__ int sh[1024];
    int t = threadIdx.x;
    int i = blockIdx.x * 1024 + t;
    int v = 0;
    if (i < NN) {
        v = g_deg[i];
        g_dis[i] = rsqrtf((float)(v + 1));
    }
    sh[t] = v;
    __syncthreads();
    for (int off = 1; off < 1024; off <<= 1) {
        int x = (t >= off) ? sh[t - off] : 0;
        __syncthreads();
        sh[t] += x;
        __syncthreads();
    }
    if (i < NN) g_rowstart[i] = sh[t] - v;       // block-local exclusive
    if (t == 1023) g_bsum[blockIdx.x] = sh[1023];
}

// each block warp-reduces the partials of preceding blocks, then offsets its
// 1024 rowstarts and seeds the fill cursors.
__global__ void k_scanB(int E) {
    __shared__ int s_off;
    int b = blockIdx.x, t = threadIdx.x;
    if (t < 32) {
        int s = 0;
        for (int k = t; k < b; k += 32) s += g_bsum[k];
#pragma unroll
        for (int o = 16; o; o >>= 1) s += __shfl_xor_sync(0xffffffffu, s, o);
        if (t == 0) s_off = s;
    }
    __syncthreads();
    int i = b * 1024 + t;
    if (i < NN) {
        int r = g_rowstart[i] + s_off;
        g_rowstart[i] = r;
        g_cursor[i]   = r;                       // cursor doubles as write pointer
    }
    if (i == NN) g_rowstart[NN] = E;
}

// 4 edges per thread: vector loads for dst+src, 4 independent atomic->store chains.
__global__ void k_fill(const void* __restrict__ ei, int E) {
    int is64 = block_is64(ei);
    int t = blockIdx.x * blockDim.x + threadIdx.x;
    int base = t * 4;
    if (base >= E) return;
    if (base + 4 <= E) {
        int d0, d1, d2, d3, s0, s1, s2, s3;
        if (is64) {
            const int4* dst = (const int4*)((const long long*)ei + E);
            const int4* src = (const int4*)((const long long*)ei);
            int4 a = dst[2 * t], b = dst[2 * t + 1];
            int4 c = src[2 * t], d = src[2 * t + 1];
            d0 = a.x; d1 = a.z; d2 = b.x; d3 = b.z;
            s0 = c.x; s1 = c.z; s2 = d.x; s3 = d.z;
        } else {
            const int4* dst = (const int4*)((const int*)ei + E);
            const int4* src = (const int4*)((const int*)ei);
            int4 a = dst[t], c = src[t];
            d0 = a.x; d1 = a.y; d2 = a.z; d3 = a.w;
            s0 = c.x; s1 = c.y; s2 = c.z; s3 = c.w;
        }
        if ((unsigned)d0 < NN) g_srcs[atomicAdd(&g_cursor[d0], 1)] = ((unsigned)s0 < NN) ? s0 : 0;
        if ((unsigned)d1 < NN) g_srcs[atomicAdd(&g_cursor[d1], 1)] = ((unsigned)s1 < NN) ? s1 : 0;
        if ((unsigned)d2 < NN) g_srcs[atomicAdd(&g_cursor[d2], 1)] = ((unsigned)s2 < NN) ? s2 : 0;
        if ((unsigned)d3 < NN) g_srcs[atomicAdd(&g_cursor[d3], 1)] = ((unsigned)s3 < NN) ? s3 : 0;
    } else {
        for (int e = base; e < E; e++) {
            int d = is64 ? (int)((const long long*)ei)[E + e] : ((const int*)ei)[E + e];
            int s = is64 ? (int)((const long long*)ei)[e]     : ((const int*)ei)[e];
            if ((unsigned)d < NN)
                g_srcs[atomicAdd(&g_cursor[d], 1)] = ((unsigned)s < NN) ? s : 0;
        }
    }
}

// ---------------- layer 1 transform: hs1 = dis[n] * (x[n] @ W1^T) ----------------
__global__ void k_gemm1(const float* __restrict__ x, const float* __restrict__ W1) {
    __shared__ float4 sW[32 * 32];                 // W1 [32,128] as float4
    for (int i = threadIdx.x; i < 1024; i += blockDim.x)
        sW[i] = ((const float4*)W1)[i];
    __syncthreads();
    int n = blockIdx.x * blockDim.x + threadIdx.x;
    if (n >= NN) return;
    float acc[32];
#pragma unroll
    for (int j = 0; j < 32; j++) acc[j] = 0.f;
    const float4* xr = (const float4*)(x + (size_t)n * 128);
#pragma unroll 8
    for (int k4 = 0; k4 < 32; k4++) {
        float4 xv = xr[k4];
#pragma unroll
        for (int j = 0; j < 32; j++) {
            float4 w = sW[j * 32 + k4];
            acc[j] += xv.x * w.x + xv.y * w.y + xv.z * w.z + xv.w * w.w;
        }
    }
    float dv = g_dis[n];
    float4* o = (float4*)(g_hs1 + (size_t)n * 32);
#pragma unroll
    for (int j = 0; j < 8; j++)
        o[j] = make_float4(acc[4*j] * dv, acc[4*j+1] * dv, acc[4*j+2] * dv, acc[4*j+3] * dv);
}

// ---------------- layer 1 aggregate: warp per node, 32 lanes = 32 feats ----------------
// Minimal inner loop: 1 coalesced LDG (one 128B line) + 1 FADD per edge (R9-proven).
__global__ void k_agg1(const float* __restrict__ b1) {
    int gt = blockIdx.x * blockDim.x + threadIdx.x;
    int v = gt >> 5, lane = threadIdx.x & 31;
    if (v >= NN) return;
    float acc = g_hs1[v * 32 + lane];              // self-loop term (already dis-scaled)
    int s0 = g_rowstart[v], s1 = g_rowstart[v + 1];
    for (int base = s0; base < s1; base += 32) {
        int idx = base + lane;
        int sv = g_srcs[idx < s1 ? idx : s1 - 1];
        int cnt = s1 - base;
        if (cnt >= 32) {
#pragma unroll
            for (int j = 0; j < 32; j++) {
                int s = __shfl_sync(0xffffffffu, sv, j);
                acc += g_hs1[s * 32 + lane];       // coalesced 128B line / edge
            }
        } else {
            for (int j = 0; j < cnt; j++) {
                int s = __shfl_sync(0xffffffffu, sv, j);
                acc += g_hs1[s * 32 + lane];
            }
        }
    }
    float r = g_dis[v] * acc + b1[lane];
    g_y1[v * 32 + lane] = fmaxf(r, 0.f);
}

// ---------------- layer 2 transform: hs2 = dis[n] * (y1[n] @ W2^T) ----------------
__global__ void k_gemm2(const float* __restrict__ W2) {
    __shared__ float sW[512];                      // W2 [16,32]
    for (int i = threadIdx.x; i < 512; i += blockDim.x) sW[i] = W2[i];
    __syncthreads();
    int n = blockIdx.x * blockDim.x + threadIdx.x;
    if (n >= NN) return;
    float xin[32];
    const float4* yr = (const float4*)(g_y1 + (size_t)n * 32);
#pragma unroll
    for (int k4 = 0; k4 < 8; k4++) {
        float4 t = yr[k4];
        xin[4*k4] = t.x; xin[4*k4+1] = t.y; xin[4*k4+2] = t.z; xin[4*k4+3] = t.w;
    }
    float dv = g_dis[n];
#pragma unroll
    for (int j = 0; j < 16; j++) {
        float a = 0.f;
#pragma unroll
        for (int k = 0; k < 32; k++) a += xin[k] * sW[j * 32 + k];
        g_hs2[n * 16 + j] = a * dv;
    }
}

// ---------------- layer 2 aggregate + fused LSTM + output proj ----------------
// 16 lanes per node; two nodes per warp (R9-proven). y2 never hits memory.
__global__ void k_agg2(const float* __restrict__ b2, const float* __restrict__ w_ih,
                       const float* __restrict__ b_ih, const float* __restrict__ b_hh,
                       const float* __restrict__ W_out, const float* __restrict__ b_out,
                       float* __restrict__ out) {
    int gt = blockIdx.x * blockDim.x + threadIdx.x;
    int v = gt >> 4;
    int lane = threadIdx.x & 31;
    int gl = lane & 15;
    unsigned gmask = 0xFFFFu << (lane & 16);       // own half-warp only (groups may diverge)
    if (v >= NN) return;

    float acc = g_hs2[v * 16 + gl];                // self-loop
    int s0 = g_rowstart[v], s1 = g_rowstart[v + 1];
    for (int base = s0; base < s1; base += 16) {
        int idx = base + gl;
        int sv = g_srcs[idx < s1 ? idx : s1 - 1];
        int cnt = s1 - base;
        if (cnt >= 16) {
#pragma unroll
            for (int j = 0; j < 16; j++) {
                int s = __shfl_sync(gmask, sv, j, 16);
                acc += g_hs2[s * 16 + gl];
            }
        } else {
            for (int j = 0; j < cnt; j++) {
                int s = __shfl_sync(gmask, sv, j, 16);
                acc += g_hs2[s * 16 + gl];
            }
        }
    }
    float y2 = fmaxf(g_dis[v] * acc + b2[gl], 0.f);

    // LSTM (h0=c0=0): gates i,g,o only (f multiplies c0=0; w_hh term zero).
    int j = gl & 7;
    float ai = b_ih[j]      + b_hh[j];
    float ag = b_ih[16 + j] + b_hh[16 + j];
    float ao = b_ih[24 + j] + b_hh[24 + j];
#pragma unroll
    for (int k = 0; k < 16; k++) {
        float vv = __shfl_sync(gmask, y2, k, 16);
        ai += w_ih[j * 16 + k]        * vv;
        ag += w_ih[(16 + j) * 16 + k] * vv;
        ao += w_ih[(24 + j) * 16 + k] * vv;
    }
    float c  = (1.f / (1.f + __expf(-ai))) * tanhf(ag);
    float hh = (1.f / (1.f + __expf(-ao))) * tanhf(c);
    float part = (gl < 8) ? hh * W_out[j] : 0.f;
#pragma unroll
    for (int off = 8; off; off >>= 1)
        part += __shfl_xor_sync(gmask, part, off, 16);
    if (gl == 0) out[v] = part + b_out[0];
}

// ---------------- launch ----------------
extern "C" void kernel_launch(void* const* d_in, const int* in_sizes, int n_in,
                              void* d_out, int out_size) {
    const float* x     = (const float*)d_in[0];
    const void*  ei    = d_in[1];
    const float* W1    = (const float*)d_in[2];
    const float* b1    = (const float*)d_in[3];
    const float* W2    = (const float*)d_in[4];
    const float* b2    = (const float*)d_in[5];
    const float* w_ih  = (const float*)d_in[6];
    // d_in[7] = w_hh: unused (h0 == 0)
    const float* b_ih  = (const float*)d_in[8];
    const float* b_hh  = (const float*)d_in[9];
    const float* W_out = (const float*)d_in[10];
    const float* b_out = (const float*)d_in[11];
    float*       out   = (float*)d_out;

    int E  = in_sizes[1] / 2;   // element count is 6.4M for both int32 and int64
    int nt = (E + 3) / 4;       // threads for 4-edges-per-thread kernels
    int nb = (NN + 1023) / 1024;

    k_init  <<<(NN + 255) / 256, 256>>>();                        // 1
    k_count <<<(nt + 255) / 256, 256>>>(ei, E);                   // 2
    k_scan1 <<<nb, 1024>>>();                                     // 3
    k_scanB <<<nb, 1024>>>(E);                                    // 4
    k_fill  <<<(nt + 255) / 256, 256>>>(ei, E);                   // 5
    k_gemm1 <<<(NN + 127) / 128, 128>>>(x, W1);                   // 6
    k_agg1  <<<(NN * 32 + 255) / 256, 256>>>(b1);                 // 7
    k_gemm2 <<<(NN + 255) / 256, 256>>>(W2);                      // 8
    k_agg2  <<<(NN * 16 + 255) / 256, 256>>>(b2, w_ih, b_ih, b_hh, W_out, b_out, out);  // 9
}